// round 16
// baseline (speedup 1.0000x reference)
#include <cuda_runtime.h>
#include <cstdint>

#define HVAL 256
#define HINGE 100.0f
#define NB 1184           // b-groups per sweep (148 SMs * 16 CTAs / 2 halves)
#define NSTAGE 2

// Single-instruction approximate sqrt (MUFU.SQRT). sqrt.approx(+0) = +0.
__device__ __forceinline__ float asqrt(float x) {
    float r;
    asm("sqrt.approx.f32 %0, %1;" : "=f"(r) : "f"(x));
    return r;
}

__device__ __forceinline__ void cp_async16(uint32_t smem_dst, const void* gmem_src) {
    asm volatile("cp.async.cg.shared.global [%0], [%1], 16;\n"
                 :: "r"(smem_dst), "l"(gmem_src));
}
__device__ __forceinline__ void cp_commit() {
    asm volatile("cp.async.commit_group;\n");
}
template<int N>
__device__ __forceinline__ void cp_wait() {
    asm volatile("cp.async.wait_group %0;\n" :: "n"(N));
}

// 128-thread CTAs, 16/SM (2048 threads = full occupancy; ptxas capped to 32 regs).
// 2-stage ring, compile-time slots. Latency hidden by 16 independent CTA
// pipelines per SM instead of deep per-CTA prefetch.
__global__ __launch_bounds__(128, 16)
void traj_cost_kernel(const float* __restrict__ pos,   // [B,H,3]
                      const float* __restrict__ rot,   // [B,H,3,3]
                      const float* __restrict__ gpos,  // [H,3]
                      const float* __restrict__ grot,  // [H,3,3]
                      float* __restrict__ out,         // [3,B*H]
                      int B)
{
    // 2-stage ring: (1152 + 384) floats * 4 B = 6.1 KB per stage, 12.3 KB total
    __shared__ float s_rot[NSTAGE][128 * 9];
    __shared__ float s_pos[NSTAGE][128 * 3];

    const int tid  = threadIdx.x;
    const int half = blockIdx.x & 1;
    const int h    = half * 128 + tid;

    // ---- Goal data: once into registers; precompute negated otg ----
    float G[9], notg[3];
    #pragma unroll
    for (int i = 0; i < 9; i++) G[i] = __ldg(&grot[h * 9 + i]);
    {
        float pg0 = __ldg(&gpos[h * 3 + 0]);
        float pg1 = __ldg(&gpos[h * 3 + 1]);
        float pg2 = __ldg(&gpos[h * 3 + 2]);
        #pragma unroll
        for (int i = 0; i < 3; i++)
            notg[i] = -fmaf(G[i], pg0, fmaf(G[3 + i], pg1, G[6 + i] * pg2));
    }

    const int b0 = blockIdx.x >> 1;
    int rof4 = b0 * 576 + half * 288;   // float4 offsets, 32-bit safe
    int pof4 = b0 * 192 + half * 96;
    int n    = b0 * HVAL + h;
    const int rstep = NB * 576;
    const int pstep = NB * 192;
    const int nstep = NB * HVAL;
    const int BH    = B * HVAL;

    const float4* rbase = reinterpret_cast<const float4*>(rot);
    const float4* pbase = reinterpret_cast<const float4*>(pos);

    float* __restrict__ out0 = out;
    float* __restrict__ out1 = out + BH;
    float* __restrict__ out2 = out + 2 * BH;

    auto stage = [&](float* rd, float* pd, int ro, int po) {
        uint32_t sr = (uint32_t)__cvta_generic_to_shared(rd);
        uint32_t sp = (uint32_t)__cvta_generic_to_shared(pd);
        cp_async16(sr + (uint32_t)(tid      ) * 16, rbase + ro + tid);
        cp_async16(sr + (uint32_t)(tid + 128) * 16, rbase + ro + tid + 128);
        if (tid < 32)
            cp_async16(sr + (uint32_t)(tid + 256) * 16, rbase + ro + tid + 256);
        if (tid < 96)
            cp_async16(sp + (uint32_t)tid * 16, pbase + po + tid);
        cp_commit();
    };

    int b = b0;

    // Prologue: stage tile 0 into slot 0 (prefetch distance 1)
    stage(s_rot[0], s_pos[0], rof4, pof4);

    while (b < B) {
        #pragma unroll
        for (int s = 0; s < NSTAGE; s++) {
            if (b >= B) break;

            // A) all warps finished consuming tile i-1 -> slot s^1 is free
            __syncthreads();

            // stage tile i+1 BEFORE waiting on tile i
            const bool has1 = (b + NB < B);
            if (has1)
                stage(s_rot[s ^ 1], s_pos[s ^ 1], rof4 + rstep, pof4 + pstep);

            // per-thread wait: own tile-i copies complete
            if (has1) cp_wait<1>(); else cp_wait<0>();

            // B) publish all threads' tile-i data
            __syncthreads();

            // consume tile i
            float R[9], p[3];
            #pragma unroll
            for (int i = 0; i < 9; i++) R[i] = s_rot[s][tid * 9 + i];
            #pragma unroll
            for (int i = 0; i < 3; i++) p[i] = s_pos[s][tid * 3 + i];

            // t[i] = (R^T p)[i] - otg[i]
            float t0 = fmaf(R[0], p[0], fmaf(R[3], p[1], fmaf(R[6], p[2], notg[0])));
            float t1 = fmaf(R[1], p[0], fmaf(R[4], p[1], fmaf(R[7], p[2], notg[1])));
            float t2 = fmaf(R[2], p[0], fmaf(R[5], p[1], fmaf(R[8], p[2], notg[2])));
            float pos_err   = fmaf(t0, t0, fmaf(t1, t1, t2 * t2));
            float goal_dist = asqrt(pos_err);

            // m' = G^T R - I (identity folded into FMA seed)
            float rsq[3];
            #pragma unroll
            for (int i = 0; i < 3; i++) {
                float acc = 0.0f;
                #pragma unroll
                for (int j = 0; j < 3; j++) {
                    float seed = (i == j) ? -1.0f : 0.0f;
                    float m = fmaf(G[i], R[j],
                              fmaf(G[3 + i], R[3 + j],
                              fmaf(G[6 + i], R[6 + j], seed)));
                    acc = fmaf(m, m, acc);
                }
                rsq[i] = acc;
            }
            float rn_sum = asqrt(rsq[0]) + asqrt(rsq[1]) + asqrt(rsq[2]);
            float rot_err_norm = asqrt(rsq[0] + rsq[1] + rsq[2]);
            float sq_rot = (goal_dist <= HINGE) ? rn_sum : 0.0f;

            __stcs(out0 + n, sq_rot + goal_dist);   // WEIGHT = (1,1)
            __stcs(out1 + n, rot_err_norm);
            __stcs(out2 + n, goal_dist);

            b    += NB;
            rof4 += rstep;
            pof4 += pstep;
            n    += nstep;
        }
    }
}

extern "C" void kernel_launch(void* const* d_in, const int* in_sizes, int n_in,
                              void* d_out, int out_size) {
    // Bind inputs BY SIZE (robust to harness ordering):
    //   H*3 -> gpos, H*9 -> grot, B*H*3 -> pos, B*H*9 -> rot
    int idx[4] = {0, 1, 2, 3};
    for (int i = 1; i < 4; i++) {
        int v = idx[i];
        int j = i - 1;
        while (j >= 0 && in_sizes[idx[j]] > in_sizes[v]) { idx[j + 1] = idx[j]; j--; }
        idx[j + 1] = v;
    }
    const float* gpos = (const float*)d_in[idx[0]];
    const float* grot = (const float*)d_in[idx[1]];
    const float* pos  = (const float*)d_in[idx[2]];
    const float* rot  = (const float*)d_in[idx[3]];

    const int H = in_sizes[idx[0]] / 3;          // 256
    const int B = in_sizes[idx[3]] / (9 * H);    // 8192

    float* out = (float*)d_out;
    traj_cost_kernel<<<2 * NB, 128>>>(pos, rot, gpos, grot, out, B);
}

// round 17
// speedup vs baseline: 1.0893x; 1.0893x over previous
#include <cuda_runtime.h>
#include <cstdint>

#define HVAL 256
#define HINGE 100.0f
#define NB 1776           // b-stride = CTAs per half (grid = 2*NB = 3552, ~2 waves)
#define NSTAGE 3

// Single-instruction approximate sqrt (MUFU.SQRT). sqrt.approx(+0) = +0.
__device__ __forceinline__ float asqrt(float x) {
    float r;
    asm("sqrt.approx.f32 %0, %1;" : "=f"(r) : "f"(x));
    return r;
}

__device__ __forceinline__ void cp_async16(uint32_t smem_dst, const void* gmem_src) {
    asm volatile("cp.async.cg.shared.global [%0], [%1], 16;\n"
                 :: "r"(smem_dst), "l"(gmem_src));
}
__device__ __forceinline__ void cp_commit() {
    asm volatile("cp.async.commit_group;\n");
}
template<int N>
__device__ __forceinline__ void cp_wait() {
    asm volatile("cp.async.wait_group %0;\n" :: "n"(N));
}

// 128-thread CTAs, 12/SM. 3-stage ring, compile-time slot indices.
// Proven R11 ordering: wait(i) -> sync (publish + retire) -> stage(i+2) -> consume(i).
// Grid oversubscribed 2x so second-wave CTAs backfill and smooth the tail.
__global__ __launch_bounds__(128, 12)
void traj_cost_kernel(const float* __restrict__ pos,   // [B,H,3]
                      const float* __restrict__ rot,   // [B,H,3,3]
                      const float* __restrict__ gpos,  // [H,3]
                      const float* __restrict__ grot,  // [H,3,3]
                      float* __restrict__ out,         // [3,B*H]
                      int B)
{
    __shared__ float s_rot[NSTAGE][128 * 9];
    __shared__ float s_pos[NSTAGE][128 * 3];

    const int tid  = threadIdx.x;
    const int half = blockIdx.x & 1;
    const int h    = half * 128 + tid;

    // ---- Goal data: once into registers; precompute negated otg ----
    float G[9], notg[3];
    #pragma unroll
    for (int i = 0; i < 9; i++) G[i] = __ldg(&grot[h * 9 + i]);
    {
        float pg0 = __ldg(&gpos[h * 3 + 0]);
        float pg1 = __ldg(&gpos[h * 3 + 1]);
        float pg2 = __ldg(&gpos[h * 3 + 2]);
        #pragma unroll
        for (int i = 0; i < 3; i++)
            notg[i] = -fmaf(G[i], pg0, fmaf(G[3 + i], pg1, G[6 + i] * pg2));
    }

    const int b0 = blockIdx.x >> 1;
    int rof4 = b0 * 576 + half * 288;   // float4 offsets, 32-bit safe
    int pof4 = b0 * 192 + half * 96;
    int n    = b0 * HVAL + h;
    const int rstep = NB * 576;
    const int pstep = NB * 192;
    const int nstep = NB * HVAL;
    const int BH    = B * HVAL;

    const float4* rbase = reinterpret_cast<const float4*>(rot);
    const float4* pbase = reinterpret_cast<const float4*>(pos);

    float* __restrict__ out0 = out;
    float* __restrict__ out1 = out + BH;
    float* __restrict__ out2 = out + 2 * BH;

    auto stage = [&](float* rd, float* pd, int ro, int po) {
        uint32_t sr = (uint32_t)__cvta_generic_to_shared(rd);
        uint32_t sp = (uint32_t)__cvta_generic_to_shared(pd);
        cp_async16(sr + (uint32_t)(tid      ) * 16, rbase + ro + tid);
        cp_async16(sr + (uint32_t)(tid + 128) * 16, rbase + ro + tid + 128);
        if (tid < 32)
            cp_async16(sr + (uint32_t)(tid + 256) * 16, rbase + ro + tid + 256);
        if (tid < 96)
            cp_async16(sp + (uint32_t)tid * 16, pbase + po + tid);
        cp_commit();
    };

    int b = b0;

    // Prologue: prefetch distance 2 into slots 0 and 1
    stage(s_rot[0], s_pos[0], rof4, pof4);
    if (b + NB < B)
        stage(s_rot[1], s_pos[1], rof4 + rstep, pof4 + pstep);

    while (b < B) {
        #pragma unroll
        for (int s = 0; s < NSTAGE; s++) {
            if (b >= B) break;

            // wait for tile i (groups i+1 may be pending)
            if (b + NB < B) cp_wait<1>(); else cp_wait<0>();
            // single barrier: publishes tile i to all warps AND guarantees
            // slot (s+2)%3 (tile i-1) is fully consumed before restaging
            __syncthreads();

            if (b + 2 * NB < B) {
                const int s2 = (s + 2) % NSTAGE;     // constant after unroll
                stage(s_rot[s2], s_pos[s2], rof4 + 2 * rstep, pof4 + 2 * pstep);
            }

            // consume tile i
            float R[9], p[3];
            #pragma unroll
            for (int i = 0; i < 9; i++) R[i] = s_rot[s][tid * 9 + i];
            #pragma unroll
            for (int i = 0; i < 3; i++) p[i] = s_pos[s][tid * 3 + i];

            // t[i] = (R^T p)[i] - otg[i]
            float t0 = fmaf(R[0], p[0], fmaf(R[3], p[1], fmaf(R[6], p[2], notg[0])));
            float t1 = fmaf(R[1], p[0], fmaf(R[4], p[1], fmaf(R[7], p[2], notg[1])));
            float t2 = fmaf(R[2], p[0], fmaf(R[5], p[1], fmaf(R[8], p[2], notg[2])));
            float pos_err   = fmaf(t0, t0, fmaf(t1, t1, t2 * t2));
            float goal_dist = asqrt(pos_err);

            // m' = G^T R - I (identity folded into FMA seed)
            float rsq[3];
            #pragma unroll
            for (int i = 0; i < 3; i++) {
                float acc = 0.0f;
                #pragma unroll
                for (int j = 0; j < 3; j++) {
                    float seed = (i == j) ? -1.0f : 0.0f;
                    float m = fmaf(G[i], R[j],
                              fmaf(G[3 + i], R[3 + j],
                              fmaf(G[6 + i], R[6 + j], seed)));
                    acc = fmaf(m, m, acc);
                }
                rsq[i] = acc;
            }
            float rn_sum = asqrt(rsq[0]) + asqrt(rsq[1]) + asqrt(rsq[2]);
            float rot_err_norm = asqrt(rsq[0] + rsq[1] + rsq[2]);
            float sq_rot = (goal_dist <= HINGE) ? rn_sum : 0.0f;

            __stcs(out0 + n, sq_rot + goal_dist);   // WEIGHT = (1,1)
            __stcs(out1 + n, rot_err_norm);
            __stcs(out2 + n, goal_dist);

            b    += NB;
            rof4 += rstep;
            pof4 += pstep;
            n    += nstep;
        }
    }
}

extern "C" void kernel_launch(void* const* d_in, const int* in_sizes, int n_in,
                              void* d_out, int out_size) {
    // Bind inputs BY SIZE (robust to harness ordering):
    //   H*3 -> gpos, H*9 -> grot, B*H*3 -> pos, B*H*9 -> rot
    int idx[4] = {0, 1, 2, 3};
    for (int i = 1; i < 4; i++) {
        int v = idx[i];
        int j = i - 1;
        while (j >= 0 && in_sizes[idx[j]] > in_sizes[v]) { idx[j + 1] = idx[j]; j--; }
        idx[j + 1] = v;
    }
    const float* gpos = (const float*)d_in[idx[0]];
    const float* grot = (const float*)d_in[idx[1]];
    const float* pos  = (const float*)d_in[idx[2]];
    const float* rot  = (const float*)d_in[idx[3]];

    const int H = in_sizes[idx[0]] / 3;          // 256
    const int B = in_sizes[idx[3]] / (9 * H);    // 8192

    float* out = (float*)d_out;
    traj_cost_kernel<<<2 * NB, 128>>>(pos, rot, gpos, grot, out, B);
}